// round 12
// baseline (speedup 1.0000x reference)
#include <cuda_runtime.h>
#include <cstdint>
#include <cstddef>

#define NB 512
#define NN 1000
#define SPL 4

using u64 = unsigned long long;

__device__ float g_Qt[NB * 1024];           // [b][h][d], 0.25 folded
__device__ short g_idx[NB * NN];            // compacted unmasked row ids
__device__ int   g_cnt[NB];
__device__ float g_part[NB * SPL * 1024];   // [b][s][h][d] weighted ctx partials
__device__ float g_denp[NB * SPL * 8];      // [b][s][h]
__device__ float g_y[NB * 128];
__device__ float g_den2[NB * SPL];

__device__ __forceinline__ u64 pack2(float lo, float hi) {
    u64 r; asm("mov.b64 %0, {%1, %2};" : "=l"(r) : "f"(lo), "f"(hi)); return r;
}
__device__ __forceinline__ void unpack2(u64 v, float& lo, float& hi) {
    asm("mov.b64 {%0, %1}, %2;" : "=f"(lo), "=f"(hi) : "l"(v));
}
__device__ __forceinline__ u64 ffma2(u64 a, u64 b, u64 c) {
    u64 d; asm("fma.rn.f32x2 %0, %1, %2, %3;" : "=l"(d) : "l"(a), "l"(b), "l"(c)); return d;
}

// ===================== K1: compact + qproj + Qt + zero out =====================
__global__ __launch_bounds__(256)
void k1_setup(const float* __restrict__ state, const int* __restrict__ mask,
              const float* __restrict__ Wq, const float* __restrict__ Wkm,
              float* __restrict__ out) {
    __shared__ __align__(16) float s_state[384];
    __shared__ __align__(16) float s_q[128];
    __shared__ __align__(16) float s_Qt[8][128];

    const int t = threadIdx.x, w = t >> 5, lane = t & 31, b = blockIdx.x;

    if (t < 128) {
        s_state[t]       = state[(size_t)b * 384 + t];
        s_state[t + 128] = state[(size_t)b * 384 + 128 + t];
        s_state[t + 256] = state[(size_t)b * 384 + 256 + t];
    }
    for (int i = t; i < NN; i += 256) out[(size_t)b * NN + i] = 0.f;
    __syncthreads();

    if (w == 0) {
        int base = 0;
        const int* mb = mask + (size_t)b * NN;
        for (int i0 = 0; i0 < NN; i0 += 32) {
            int n = i0 + lane;
            int m = (n < NN) ? __ldg(&mb[n]) : 1;
            unsigned bal = __ballot_sync(0xffffffffu, m == 0);
            if (m == 0) {
                int pre = __popc(bal & ((1u << lane) - 1u));
                g_idx[(size_t)b * NN + base + pre] = (short)n;
            }
            base += __popc(bal);
        }
        if (lane == 0) g_cnt[b] = base;
    } else if (t >= 128) {
        int col = t - 128;
        float a0 = 0.f, a1 = 0.f, a2 = 0.f, a3 = 0.f;
        #pragma unroll 4
        for (int i = 0; i < 384; i += 4) {
            a0 = fmaf(s_state[i    ], __ldg(&Wq[(i    ) * 128 + col]), a0);
            a1 = fmaf(s_state[i + 1], __ldg(&Wq[(i + 1) * 128 + col]), a1);
            a2 = fmaf(s_state[i + 2], __ldg(&Wq[(i + 2) * 128 + col]), a2);
            a3 = fmaf(s_state[i + 3], __ldg(&Wq[(i + 3) * 128 + col]), a3);
        }
        s_q[col] = (a0 + a1) + (a2 + a3);
    }
    __syncthreads();

    {   // Qt[h][d] = 0.25 * sum_j Wkm[d][16h+j] * q[16h+j]
        const int hw    = w & 3;
        const int dbase = (w >> 2) * 64;
        const int hid   = hw * 32 + lane;
        const float ql  = s_q[hid];
        const int head0 = hw * 2 + (lane >> 4);
        #pragma unroll 4
        for (int dd = 0; dd < 64; dd++) {
            int d = dbase + dd;
            float p = __ldg(&Wkm[d * 128 + hid]) * ql;
            p += __shfl_xor_sync(0xffffffffu, p, 8);
            p += __shfl_xor_sync(0xffffffffu, p, 4);
            p += __shfl_xor_sync(0xffffffffu, p, 2);
            p += __shfl_xor_sync(0xffffffffu, p, 1);
            if ((lane & 15) == 0) s_Qt[head0][d] = 0.25f * p;
        }
    }
    __syncthreads();
    for (int i = t; i < 1024; i += 256) g_Qt[(size_t)b * 1024 + i] = s_Qt[i >> 7][i & 127];
}

// ===================== K2: pass 1 (split), 4 heads per warp =====================
__global__ __launch_bounds__(256, 4)
void k2_pass1(const float* __restrict__ ctx) {
    __shared__ __align__(16) float s_Qt[8][128];
    __shared__ short s_il[256];
    __shared__ __align__(16) float s_red[8][4][128];   // [warp][local head][d]
    __shared__ float s_dred[8][4];

    const int t = threadIdx.x, w = t >> 5, lane = t & 31;
    const int b = blockIdx.y, s = blockIdx.x;
    const int cnt = g_cnt[b];
    const int js = (cnt * s) / SPL, je = (cnt * (s + 1)) / SPL;
    const int nrows = je - js;

    for (int i = t; i < 1024; i += 256) (&s_Qt[0][0])[i] = g_Qt[(size_t)b * 1024 + i];
    for (int i = t; i < nrows; i += 256) s_il[i] = g_idx[(size_t)b * NN + js + i];
    __syncthreads();

    const int g  = w >> 1;       // row group (stride 4)
    const int hf = w & 1;        // head half: heads hf*4 .. hf*4+3
    u64 qt2[4][2], acc[4][2];
    #pragma unroll
    for (int i = 0; i < 4; i++) {
        float4 qv = *reinterpret_cast<const float4*>(&s_Qt[hf * 4 + i][lane * 4]);
        qt2[i][0] = pack2(qv.x, qv.y);
        qt2[i][1] = pack2(qv.z, qv.w);
        acc[i][0] = 0ull; acc[i][1] = 0ull;
    }
    float den_l = 0.f;

    const float4* ctx4 = reinterpret_cast<const float4*>(ctx + (size_t)b * NN * 128);

    auto doRow = [&](float4 c, bool valid) {
        u64 cA = pack2(c.x, c.y), cB = pack2(c.z, c.w);
        float p[4];
        #pragma unroll
        for (int i = 0; i < 4; i++) {
            u64 sd = ffma2(cA, qt2[i][0], ffma2(cB, qt2[i][1], 0ull));
            float lo, hi; unpack2(sd, lo, hi);
            p[i] = lo + hi;
        }
        // 4-value butterfly: 6 shfl
        #pragma unroll
        for (int i = 0; i < 2; i++) {
            float send = (lane & 16) ? p[i] : p[i + 2];
            float keep = (lane & 16) ? p[i + 2] : p[i];
            p[i] = keep + __shfl_xor_sync(0xffffffffu, send, 16);
        }
        {
            float send = (lane & 8) ? p[0] : p[1];
            float keep = (lane & 8) ? p[1] : p[0];
            p[0] = keep + __shfl_xor_sync(0xffffffffu, send, 8);
        }
        p[0] += __shfl_xor_sync(0xffffffffu, p[0], 4);
        p[0] += __shfl_xor_sync(0xffffffffu, p[0], 2);
        p[0] += __shfl_xor_sync(0xffffffffu, p[0], 1);
        // lane holds head hl = 2*bit4 + bit3 (lanes 0,8,16,24 -> hl 0..3)
        float e = valid ? __expf(p[0]) : 0.f;
        if ((lane & 7) == 0) den_l += e;
        float eh[4];
        #pragma unroll
        for (int i = 0; i < 4; i++) eh[i] = __shfl_sync(0xffffffffu, e, i * 8);
        #pragma unroll
        for (int i = 0; i < 4; i++) {
            u64 e2 = pack2(eh[i], eh[i]);
            acc[i][0] = ffma2(e2, cA, acc[i][0]);
            acc[i][1] = ffma2(e2, cB, acc[i][1]);
        }
    };

    for (int k = g; k < nrows; k += 8) {
        int kB = k + 4;
        bool vB = kB < nrows;
        int nA = s_il[k];
        int nB = vB ? s_il[kB] : nA;
        float4 cA4 = __ldg(ctx4 + nA * 32 + lane);
        float4 cB4 = __ldg(ctx4 + nB * 32 + lane);
        doRow(cA4, true);
        doRow(cB4, vB);
    }

    #pragma unroll
    for (int i = 0; i < 4; i++) {
        float x0, x1, x2, x3;
        unpack2(acc[i][0], x0, x1); unpack2(acc[i][1], x2, x3);
        *reinterpret_cast<float4*>(&s_red[w][i][lane * 4]) = make_float4(x0, x1, x2, x3);
    }
    if ((lane & 7) == 0) s_dred[w][lane >> 3] = den_l;
    __syncthreads();

    float* partb = g_part + ((size_t)b * SPL + s) * 1024;
    for (int i = t; i < 1024; i += 256) {
        int h = i >> 7, d = i & 127;
        int hf2 = h >> 2, hl = h & 3;
        partb[i] = (s_red[hf2][hl][d] + s_red[2 + hf2][hl][d]) +
                   (s_red[4 + hf2][hl][d] + s_red[6 + hf2][hl][d]);
    }
    if (t < 8) {
        int hf2 = t >> 2, hl = t & 3;
        g_denp[((size_t)b * SPL + s) * 8 + t] =
            (s_dred[hf2][hl] + s_dred[2 + hf2][hl]) +
            (s_dred[4 + hf2][hl] + s_dred[6 + hf2][hl]);
    }
}

// ===================== K3: reduce partials + GEMV chain -> y =====================
__global__ __launch_bounds__(256)
void k3_mid(const float* __restrict__ Wv, const float* __restrict__ Wfc,
            const float* __restrict__ Wk) {
    __shared__ __align__(16) float s_sun[8][128];
    __shared__ float s_denf[8];
    __shared__ __align__(16) float s_x128[2][128];
    __shared__ __align__(16) float s_xfc[2][128];

    const int t = threadIdx.x, w = t >> 5, lane = t & 31, b = blockIdx.x;

    for (int i = t; i < 1024; i += 256) {
        const float* pb = g_part + (size_t)b * SPL * 1024 + i;
        (&s_sun[0][0])[i] = (pb[0] + pb[1024]) + (pb[2048] + pb[3072]);
    }
    if (t < 8) {
        const float* dp = g_denp + (size_t)b * SPL * 8 + t;
        s_denf[t] = (dp[0] + dp[8]) + (dp[16] + dp[24]);
    }
    __syncthreads();

    {   // x128[hid] = (sum_d sun[h][d]*Wv[d][hid]) / den[h]
        int col = t & 127, half = t >> 7, h = col >> 4;
        int db = half * 64;
        float a0 = 0.f, a1 = 0.f;
        #pragma unroll 8
        for (int d = 0; d < 64; d += 2) {
            a0 = fmaf(s_sun[h][db + d],     __ldg(&Wv[(db + d)     * 128 + col]), a0);
            a1 = fmaf(s_sun[h][db + d + 1], __ldg(&Wv[(db + d + 1) * 128 + col]), a1);
        }
        s_x128[half][col] = a0 + a1;
    }
    __syncthreads();
    if (t < 128) s_x128[0][t] = (s_x128[0][t] + s_x128[1][t]) / s_denf[t >> 4];
    __syncthreads();

    {   // xfc = x128 @ Wfc
        int col = t & 127, half = t >> 7;
        int hb = half * 64;
        float a0 = 0.f, a1 = 0.f;
        #pragma unroll 8
        for (int i = 0; i < 64; i += 2) {
            a0 = fmaf(s_x128[0][hb + i],     __ldg(&Wfc[(hb + i)     * 128 + col]), a0);
            a1 = fmaf(s_x128[0][hb + i + 1], __ldg(&Wfc[(hb + i + 1) * 128 + col]), a1);
        }
        s_xfc[half][col] = a0 + a1;
    }
    __syncthreads();
    if (t < 128) s_xfc[0][t] = s_xfc[0][t] + s_xfc[1][t];
    __syncthreads();

    {   // y[d] = nrm * sum_hid Wk[d][hid] * xfc[hid]
        const float nrm = 0.088388347648318447f;  // 1/sqrt(128)
        float4 xv = *reinterpret_cast<const float4*>(&s_xfc[0][lane * 4]);
        #pragma unroll 4
        for (int dd = 0; dd < 16; dd++) {
            int d = w * 16 + dd;
            float4 wv = __ldg(reinterpret_cast<const float4*>(&Wk[d * 128 + lane * 4]));
            float p = fmaf(wv.w, xv.w, fmaf(wv.z, xv.z, fmaf(wv.y, xv.y, wv.x * xv.x)));
            p += __shfl_xor_sync(0xffffffffu, p, 16);
            p += __shfl_xor_sync(0xffffffffu, p, 8);
            p += __shfl_xor_sync(0xffffffffu, p, 4);
            p += __shfl_xor_sync(0xffffffffu, p, 2);
            p += __shfl_xor_sync(0xffffffffu, p, 1);
            if (lane == 0) g_y[(size_t)b * 128 + d] = p * nrm;
        }
    }
}

// ===================== K4: pass 2 (split) =====================
__global__ __launch_bounds__(256)
void k4_pass2(const float* __restrict__ ctx, const int* __restrict__ Tp,
              float* __restrict__ out) {
    __shared__ __align__(16) float s_y[128];
    __shared__ short s_il[256];
    __shared__ float s_d2[8];

    const int t = threadIdx.x, w = t >> 5, lane = t & 31;
    const int b = blockIdx.y, s = blockIdx.x;
    const int cnt = g_cnt[b];
    const int js = (cnt * s) / SPL, je = (cnt * (s + 1)) / SPL;
    const int nrows = je - js;

    if (t < 128) s_y[t] = g_y[(size_t)b * 128 + t];
    for (int i = t; i < nrows; i += 256) s_il[i] = g_idx[(size_t)b * NN + js + i];
    __syncthreads();

    float Tf = 1.f;
    if (Tp) {
        unsigned r = *reinterpret_cast<const unsigned*>(Tp);
        float asf = __uint_as_float(r);
        Tf = (asf > 0.0078125f && asf < 1024.f) ? asf : (float)(int)r;
        if (!(Tf > 0.f)) Tf = 1.f;
    }
    const float invT = 1.0f / Tf;

    float4 yv = *reinterpret_cast<const float4*>(&s_y[lane * 4]);
    u64 y2a = pack2(yv.x, yv.y), y2b = pack2(yv.z, yv.w);
    float den2_l = 0.f;

    const float4* ctx4 = reinterpret_cast<const float4*>(ctx + (size_t)b * NN * 128);
    float* outb = out + (size_t)b * NN;

    auto doRow = [&](float4 c, int n, bool valid) {
        u64 A = ffma2(pack2(c.x, c.y), y2a, ffma2(pack2(c.z, c.w), y2b, 0ull));
        float lo, hi; unpack2(A, lo, hi);
        float p = lo + hi;
        p += __shfl_xor_sync(0xffffffffu, p, 16);
        p += __shfl_xor_sync(0xffffffffu, p, 8);
        p += __shfl_xor_sync(0xffffffffu, p, 4);
        p += __shfl_xor_sync(0xffffffffu, p, 2);
        p += __shfl_xor_sync(0xffffffffu, p, 1);
        float tt = __expf(2.f * p);
        float th = 1.f - __fdividef(2.f, tt + 1.f);  // tanh, inf-safe
        float pr = __expf(5.f * th * invT);
        if (valid && lane == 0) {
            outb[n] = pr;
            den2_l += pr;
        }
    };

    for (int k = w; k < nrows; k += 16) {
        int kB = k + 8;
        bool vB = kB < nrows;
        int nA = s_il[k];
        int nB = vB ? s_il[kB] : nA;
        float4 cA4 = __ldg(ctx4 + nA * 32 + lane);
        float4 cB4 = __ldg(ctx4 + nB * 32 + lane);
        doRow(cA4, nA, true);
        doRow(cB4, nB, vB);
    }
    if (lane == 0) s_d2[w] = den2_l;
    __syncthreads();
    if (t == 0) {
        float sum = 0.f;
        #pragma unroll
        for (int ww = 0; ww < 8; ww++) sum += s_d2[ww];
        g_den2[(size_t)b * SPL + s] = sum;
    }
}

// ===================== K5: normalize =====================
__global__ __launch_bounds__(256)
void k5_norm(float* __restrict__ out) {
    __shared__ float s_inv;
    const int t = threadIdx.x, b = blockIdx.x;
    if (t == 0) {
        const float* d2 = g_den2 + (size_t)b * SPL;
        s_inv = 1.0f / ((d2[0] + d2[1]) + (d2[2] + d2[3]));
    }
    __syncthreads();
    const float inv = s_inv;
    float* outb = out + (size_t)b * NN;
    for (int i = t; i < NN; i += 256) outb[i] *= inv;
}

extern "C" void kernel_launch(void* const* d_in, const int* in_sizes, int n_in,
                              void* d_out, int out_size) {
    (void)in_sizes; (void)out_size;
    const float* state = (const float*)d_in[0];
    const float* ctx   = (const float*)d_in[1];
    const int*   mask  = (const int*)d_in[2];
    const float* Wq    = (const float*)d_in[3];
    const float* Wkm   = (const float*)d_in[4];
    const float* Wv    = (const float*)d_in[5];
    const float* Wfc   = (const float*)d_in[6];
    const float* Wk    = (const float*)d_in[7];
    const int*   Tp    = (n_in > 8) ? (const int*)d_in[8] : nullptr;
    float* out = (float*)d_out;

    k1_setup<<<NB, 256>>>(state, mask, Wq, Wkm, out);
    k2_pass1<<<dim3(SPL, NB), 256>>>(ctx);
    k3_mid<<<NB, 256>>>(Wv, Wfc, Wk);
    k4_pass2<<<dim3(SPL, NB), 256>>>(ctx, Tp, out);
    k5_norm<<<NB, 256>>>(out);
}